// round 3
// baseline (speedup 1.0000x reference)
#include <cuda_runtime.h>

#define NROWS  524288
#define IND    64
#define OUTD   128
#define TILE   128
#define NTHREADS 256
#define NGRID  2048
#define TPC    (NROWS / TILE / NGRID)   // 2 tiles per CTA

// Dynamic smem layout (floats):
//   c_s   [IND][OUTD]      : 64*128          = 8192   (centers, transposed)
//   x_s   [TILE][IND+4]    : 128*68          = 8704   (x tile, padded pitch)
//   rbf_s [TILE][OUTD]     : 128*128         = 16384
//   half_c2 [OUTD]         : 128
//   half_x2 [TILE]         : 128
#define SMEM_FLOATS (IND*OUTD + TILE*(IND+4) + TILE*OUTD + OUTD + TILE)
#define SMEM_BYTES  (SMEM_FLOATS * 4)

__global__ void zero_kernel(float* out) {
    int i = blockIdx.x * blockDim.x + threadIdx.x;
    if (i < OUTD * IND) out[i] = 0.0f;
}

__global__ __launch_bounds__(NTHREADS, 1)
void rbf_hist_kernel(const float* __restrict__ xg,
                     const float* __restrict__ cg,
                     float* __restrict__ out) {
    extern __shared__ float sm[];
    float (*c_s)[OUTD]   = (float(*)[OUTD])sm;
    float (*x_s)[IND+4]  = (float(*)[IND+4])(sm + IND*OUTD);
    float (*rbf_s)[OUTD] = (float(*)[OUTD])(sm + IND*OUTD + TILE*(IND+4));
    float* half_c2 = sm + IND*OUTD + TILE*(IND+4) + TILE*OUTD;
    float* half_x2 = half_c2 + OUTD;

    const int t = threadIdx.x;

    // Load centers transposed: c_s[i][o] = c[o][i]
    #pragma unroll
    for (int idx = t; idx < OUTD * IND; idx += NTHREADS) {
        int o = idx >> 6;
        int i = idx & 63;
        c_s[i][o] = cg[idx];
    }
    __syncthreads();
    if (t < OUTD) {
        float s = 0.f;
        #pragma unroll
        for (int k = 0; k < IND; k++) { float v = c_s[k][t]; s += v * v; }
        half_c2[t] = 0.5f * s;
    }
    __syncthreads();

    // Phase-2 ownership: o in [o4,o4+4), i in [i8,i8+8)
    const int o4  = (t & 31) * 4;
    const int i8  = (t >> 5) * 8;
    // Phase-1 ownership: 8x8 block of (n,o)
    const int p1n = (t >> 4) * 8;
    const int p1o = (t & 15) * 8;

    float hist[4][8];
    #pragma unroll
    for (int a = 0; a < 4; a++)
        #pragma unroll
        for (int b = 0; b < 8; b++) hist[a][b] = 0.f;

    for (int tile = 0; tile < TPC; tile++) {
        const int row0 = (blockIdx.x * TPC + tile) * TILE;

        // Load x tile: 128 rows x 64 f32 = 2048 float4, 8 per thread, coalesced
        const float4* xg4 = (const float4*)(xg + (size_t)row0 * IND);
        #pragma unroll
        for (int j = 0; j < 8; j++) {
            int idx = t + j * NTHREADS;       // 0..2047
            int r   = idx >> 4;               // 16 float4 per row
            int c4  = idx & 15;
            float4 v = xg4[idx];
            *(float4*)&x_s[r][c4 * 4] = v;
        }
        __syncthreads();

        if (t < TILE) {
            float s = 0.f;
            #pragma unroll
            for (int k = 0; k < IND; k++) { float v = x_s[t][k]; s += v * v; }
            half_x2[t] = 0.5f * s;
        }
        __syncthreads();

        // ---- Phase 1: S[n][o] = x_n . c_o  (8x8 register block) ----
        float acc[8][8];
        #pragma unroll
        for (int a = 0; a < 8; a++)
            #pragma unroll
            for (int b = 0; b < 8; b++) acc[a][b] = 0.f;

        #pragma unroll 4
        for (int k = 0; k < IND; k++) {
            float xv[8];
            #pragma unroll
            for (int j = 0; j < 8; j++) xv[j] = x_s[p1n + j][k];
            float4 ca = *(const float4*)&c_s[k][p1o];
            float4 cb = *(const float4*)&c_s[k][p1o + 4];
            float cv[8] = {ca.x, ca.y, ca.z, ca.w, cb.x, cb.y, cb.z, cb.w};
            #pragma unroll
            for (int jn = 0; jn < 8; jn++)
                #pragma unroll
                for (int jo = 0; jo < 8; jo++)
                    acc[jn][jo] = fmaf(xv[jn], cv[jo], acc[jn][jo]);
        }

        // rbf = exp(x.c - |x|^2/2 - |c|^2/2)
        #pragma unroll
        for (int jn = 0; jn < 8; jn++) {
            float hx = half_x2[p1n + jn];
            #pragma unroll
            for (int jo = 0; jo < 8; jo++) {
                rbf_s[p1n + jn][p1o + jo] =
                    __expf(acc[jn][jo] - hx - half_c2[p1o + jo]);
            }
        }
        __syncthreads();

        // ---- Phase 2: hist[o][i] += sum_n rbf[n][o] * x[n][i] ----
        #pragma unroll 4
        for (int n = 0; n < TILE; n++) {
            float4 r4 = *(const float4*)&rbf_s[n][o4];
            float4 xa = *(const float4*)&x_s[n][i8];
            float4 xb = *(const float4*)&x_s[n][i8 + 4];
            float rv[4] = {r4.x, r4.y, r4.z, r4.w};
            float xv[8] = {xa.x, xa.y, xa.z, xa.w, xb.x, xb.y, xb.z, xb.w};
            #pragma unroll
            for (int a = 0; a < 4; a++)
                #pragma unroll
                for (int b = 0; b < 8; b++)
                    hist[a][b] = fmaf(rv[a], xv[b], hist[a][b]);
        }
        __syncthreads();   // protect x_s / rbf_s before next tile
    }

    #pragma unroll
    for (int a = 0; a < 4; a++)
        #pragma unroll
        for (int b = 0; b < 8; b++)
            atomicAdd(&out[(o4 + a) * IND + i8 + b], hist[a][b]);
}

extern "C" void kernel_launch(void* const* d_in, const int* in_sizes, int n_in,
                              void* d_out, int out_size) {
    const float* x = (const float*)d_in[0];   // [524288, 64] f32
    const float* c = (const float*)d_in[1];   // [128, 64]    f32
    float* out = (float*)d_out;               // [128, 64]    f32

    cudaFuncSetAttribute(rbf_hist_kernel,
                         cudaFuncAttributeMaxDynamicSharedMemorySize, SMEM_BYTES);

    zero_kernel<<<(OUTD * IND + 255) / 256, 256>>>(out);
    rbf_hist_kernel<<<NGRID, NTHREADS, SMEM_BYTES>>>(x, c, out);
}